// round 14
// baseline (speedup 1.0000x reference)
#include <cuda_runtime.h>
#include <cuda_bf16.h>
#include <cstdint>
#include <cstddef>

#define TT 1024
#define BB 64
#define DD 512
#define HH 512

// Recurrence partition: NI batch-groups (clusters) x NJ hidden-slices
#define NI 16
#define NJ 8
#define BSL (BB / NI)        // 4 batch rows per group
#define HSL (HH / NJ)        // 64 hidden units per slice
#define KC  4                // k-chunks of 128 per CTA
#define SLICE_BYTES (BSL * HSL * 4)
#define HS_BYTES (NJ * SLICE_BYTES)

// Device scratch (no cudaMalloc allowed)
__device__ float g_Z [(size_t)TT * BB * HH];
__device__ __nv_bfloat16 g_Ahi[(size_t)TT * BB * DD];
__device__ __nv_bfloat16 g_Alo[(size_t)TT * BB * DD];
__device__ __nv_bfloat16 g_Whi[(size_t)HH * DD];
__device__ __nv_bfloat16 g_Wlo[(size_t)HH * DD];

// ---------------------------------------------------------------------------
// PTX helpers
// ---------------------------------------------------------------------------
__device__ __forceinline__ uint32_t smem_u32(const void* p) {
    uint32_t a;
    asm("{ .reg .u64 t; cvta.to.shared.u64 t, %1; cvt.u32.u64 %0, t; }"
        : "=r"(a) : "l"(p));
    return a;
}
__device__ __forceinline__ uint32_t mapa_u32(uint32_t addr, uint32_t rank) {
    uint32_t r;
    asm("mapa.shared::cluster.u32 %0, %1, %2;" : "=r"(r) : "r"(addr), "r"(rank));
    return r;
}
__device__ __forceinline__ void mbar_init(uint32_t mbar, uint32_t cnt) {
    asm volatile("mbarrier.init.shared.b64 [%0], %1;" :: "r"(mbar), "r"(cnt) : "memory");
}
__device__ __forceinline__ void mbar_arrive_expect_tx(uint32_t mbar, uint32_t tx) {
    asm volatile("mbarrier.arrive.expect_tx.shared.b64 _, [%0], %1;"
                 :: "r"(mbar), "r"(tx) : "memory");
}
__device__ __forceinline__ void mbar_wait_parity(uint32_t mbar, uint32_t parity) {
    asm volatile(
        "{\n\t"
        ".reg .pred P;\n\t"
        "WAIT_%=:\n\t"
        "mbarrier.try_wait.parity.acquire.cta.shared::cta.b64 P, [%0], %1, 0x989680;\n\t"
        "@P bra.uni DONE_%=;\n\t"
        "bra.uni WAIT_%=;\n\t"
        "DONE_%=:\n\t"
        "}"
        :: "r"(mbar), "r"(parity) : "memory");
}
__device__ __forceinline__ void bulk_dsmem(uint32_t dst_cluster, uint32_t src_cta,
                                           uint32_t bytes, uint32_t mbar_cluster) {
    asm volatile(
        "cp.async.bulk.shared::cluster.shared::cta.mbarrier::complete_tx::bytes "
        "[%0], [%1], %2, [%3];"
        :: "r"(dst_cluster), "r"(src_cta), "r"(bytes), "r"(mbar_cluster) : "memory");
}
__device__ __forceinline__ void fence_proxy_async_cta() {
    asm volatile("fence.proxy.async.shared::cta;" ::: "memory");
}
__device__ __forceinline__ void ffma2(unsigned long long& d,
                                      unsigned long long a, unsigned long long b) {
    asm("fma.rn.f32x2 %0, %1, %2, %0;" : "+l"(d) : "l"(a), "l"(b));
}
__device__ __forceinline__ unsigned long long pack_f2(float lo, float hi) {
    return (unsigned long long)__float_as_uint(lo) |
           ((unsigned long long)__float_as_uint(hi) << 32);
}
__device__ __forceinline__ float lo_f(unsigned long long v) {
    return __uint_as_float((unsigned int)v);
}
__device__ __forceinline__ float hi_f(unsigned long long v) {
    return __uint_as_float((unsigned int)(v >> 32));
}

// mma.sync m16n8k16 bf16 (sm_80+ baseline PTX: safe at compute_103)
__device__ __forceinline__ void mma16816(float* d, const uint32_t* a, const uint32_t* b) {
    asm volatile(
        "mma.sync.aligned.m16n8k16.row.col.f32.bf16.bf16.f32 "
        "{%0,%1,%2,%3}, {%4,%5,%6,%7}, {%8,%9}, {%0,%1,%2,%3};"
        : "+f"(d[0]), "+f"(d[1]), "+f"(d[2]), "+f"(d[3])
        : "r"(a[0]), "r"(a[1]), "r"(a[2]), "r"(a[3]), "r"(b[0]), "r"(b[1]));
}
__device__ __forceinline__ void ldsm_x4(uint32_t* r, uint32_t addr) {
    asm volatile("ldmatrix.sync.aligned.m8n8.x4.shared.b16 {%0,%1,%2,%3}, [%4];"
        : "=r"(r[0]), "=r"(r[1]), "=r"(r[2]), "=r"(r[3]) : "r"(addr));
}

// ---------------------------------------------------------------------------
// Split-bf16 conversion (weights only)
// ---------------------------------------------------------------------------
__global__ void split_kernel(const float* __restrict__ src,
                             __nv_bfloat16* __restrict__ hi,
                             __nv_bfloat16* __restrict__ lo, int n)
{
    int idx = blockIdx.x * blockDim.x + threadIdx.x;
    int stride = gridDim.x * blockDim.x;
    for (int i = idx; i < n; i += stride) {
        float x = src[i];
        __nv_bfloat16 h = __float2bfloat16(x);
        hi[i] = h;
        lo[i] = __float2bfloat16(x - __bfloat162float(h));
    }
}

// ---------------------------------------------------------------------------
// HMMA GEMM (EXACT R10 static-smem version — the 6440-us component)
// ---------------------------------------------------------------------------
#define KB 32
#define PAD 40

__global__ __launch_bounds__(256) void mma_gemm_kernel(
    const float* __restrict__ Af32,
    const __nv_bfloat16* __restrict__ Ahi, const __nv_bfloat16* __restrict__ Alo,
    const __nv_bfloat16* __restrict__ Whi, const __nv_bfloat16* __restrict__ Wlo,
    const float* __restrict__ b1, const float* __restrict__ b2,
    float* __restrict__ C)
{
    __shared__ __nv_bfloat16 sAh[128][PAD];
    __shared__ __nv_bfloat16 sAl[128][PAD];
    __shared__ __nv_bfloat16 sWh[128][PAD];
    __shared__ __nv_bfloat16 sWl[128][PAD];

    const int tid   = threadIdx.x;
    const int wid   = tid >> 5;
    const int lane  = tid & 31;
    const int m0    = blockIdx.x * 128;
    const int n0    = blockIdx.y * 128;
    const int wm    = (wid >> 2) * 64;
    const int wn    = (wid & 3) * 32;

    float acc[4][4][4];
#pragma unroll
    for (int i = 0; i < 4; i++)
#pragma unroll
        for (int j = 0; j < 4; j++)
#pragma unroll
            for (int r = 0; r < 4; r++) acc[i][j][r] = 0.0f;

    const int ar = lane & 15, ac = (lane >> 4) * 8;
    const int br = (lane & 7) + ((lane >> 4) << 3), bc = ((lane >> 3) & 1) * 8;

    for (int kb = 0; kb < DD / KB; kb++) {
        const int k0 = kb * KB;

        // ---- A tiles ----
        if (Af32) {
#pragma unroll
            for (int it = 0; it < 4; it++) {
                int idx = it * 256 + tid;
                int r   = idx >> 3;
                int c4  = (idx & 7) * 4;
                float4 v = *(const float4*)(Af32 + (size_t)(m0 + r) * DD + k0 + c4);
                __nv_bfloat16 hx = __float2bfloat16(v.x);
                __nv_bfloat16 hy = __float2bfloat16(v.y);
                __nv_bfloat16 hz = __float2bfloat16(v.z);
                __nv_bfloat16 hw = __float2bfloat16(v.w);
                *(__nv_bfloat162*)&sAh[r][c4]     = __nv_bfloat162(hx, hy);
                *(__nv_bfloat162*)&sAh[r][c4 + 2] = __nv_bfloat162(hz, hw);
                __nv_bfloat162 l0, l1;
                l0.x = __float2bfloat16(v.x - __bfloat162float(hx));
                l0.y = __float2bfloat16(v.y - __bfloat162float(hy));
                l1.x = __float2bfloat16(v.z - __bfloat162float(hz));
                l1.y = __float2bfloat16(v.w - __bfloat162float(hw));
                *(__nv_bfloat162*)&sAl[r][c4]     = l0;
                *(__nv_bfloat162*)&sAl[r][c4 + 2] = l1;
            }
        } else {
#pragma unroll
            for (int tile = 0; tile < 2; tile++) {
                const __nv_bfloat16* src = (tile == 0) ? Ahi : Alo;
                __nv_bfloat16 (*dst)[PAD] = (tile == 0) ? sAh : sAl;
#pragma unroll
                for (int it = 0; it < 2; it++) {
                    int idx = it * 256 + tid;
                    int r   = idx >> 2;
                    int c   = (idx & 3) * 8;
                    uint4 v = *(const uint4*)(src + (size_t)(m0 + r) * DD + k0 + c);
                    *(uint4*)&dst[r][c] = v;
                }
            }
        }

        // ---- W tiles ----
#pragma unroll
        for (int tile = 0; tile < 2; tile++) {
            const __nv_bfloat16* src = (tile == 0) ? Whi : Wlo;
            __nv_bfloat16 (*dst)[PAD] = (tile == 0) ? sWh : sWl;
#pragma unroll
            for (int it = 0; it < 2; it++) {
                int idx = it * 256 + tid;
                int r   = idx >> 2;
                int c   = (idx & 3) * 8;
                uint4 v = *(const uint4*)(src + (size_t)(n0 + r) * DD + k0 + c);
                *(uint4*)&dst[r][c] = v;
            }
        }
        __syncthreads();

#pragma unroll
        for (int ks = 0; ks < 2; ks++) {
            const int kk = ks * 16;
            uint32_t fAh[4][4], fAl[4][4], fWh[2][4], fWl[2][4];
#pragma unroll
            for (int mf = 0; mf < 4; mf++) {
                ldsm_x4(fAh[mf], smem_u32(&sAh[wm + mf * 16 + ar][kk + ac]));
                ldsm_x4(fAl[mf], smem_u32(&sAl[wm + mf * 16 + ar][kk + ac]));
            }
#pragma unroll
            for (int np = 0; np < 2; np++) {
                ldsm_x4(fWh[np], smem_u32(&sWh[wn + np * 16 + br][kk + bc]));
                ldsm_x4(fWl[np], smem_u32(&sWl[wn + np * 16 + br][kk + bc]));
            }
#pragma unroll
            for (int mf = 0; mf < 4; mf++) {
#pragma unroll
                for (int np = 0; np < 2; np++) {
#pragma unroll
                    for (int h = 0; h < 2; h++) {
                        const int nf = np * 2 + h;
                        mma16816(acc[mf][nf], fAh[mf], &fWh[np][h * 2]);
                        mma16816(acc[mf][nf], fAh[mf], &fWl[np][h * 2]);
                        mma16816(acc[mf][nf], fAl[mf], &fWh[np][h * 2]);
                    }
                }
            }
        }
        __syncthreads();
    }

    const int erow = lane >> 2;
    const int ecol = (lane & 3) * 2;
#pragma unroll
    for (int mf = 0; mf < 4; mf++) {
#pragma unroll
        for (int nf = 0; nf < 4; nf++) {
            const int n = n0 + wn + nf * 8 + ecol;
            const float bv0 = __ldg(b1 + n)     + __ldg(b2 + n);
            const float bv1 = __ldg(b1 + n + 1) + __ldg(b2 + n + 1);
            const int r0 = m0 + wm + mf * 16 + erow;
            float2 o0 = make_float2(acc[mf][nf][0] + bv0, acc[mf][nf][1] + bv1);
            float2 o1 = make_float2(acc[mf][nf][2] + bv0, acc[mf][nf][3] + bv1);
            *(float2*)(C + (size_t)r0 * HH + n)       = o0;
            *(float2*)(C + (size_t)(r0 + 8) * HH + n) = o1;
        }
    }
}

// ---------------------------------------------------------------------------
// Persistent recurrence kernel v6: ONE barrier per step.
// - red[] double-buffered by t&1 (removes the need for the stage barrier).
// - Each warp ships its own contiguous 128B stage chunk: after __syncwarp,
//   lanes 0..7 each issue one 128B DSMEM bulk copy to one peer CTA.
//   Early warps ship while late warps still compute (no convoy).
// - expect_tx per slice remains SLICE_BYTES (8 warps x 128B = 1024B).
// Safety: stage/red reuse at t+2 is fenced by bar1(t+1)/bar1(t+2) plus the
// wait-causality chain (peers ship step t+1 only after their bar1(t+1),
// which requires our step-t shipment delivered).
// ---------------------------------------------------------------------------
__global__ __launch_bounds__(256, 1) __cluster_dims__(NJ, 1, 1)
void recur_kernel(
    const float* __restrict__ Z, const float* __restrict__ Whh,
    float* __restrict__ Yf,
    __nv_bfloat16* __restrict__ Yhi, __nv_bfloat16* __restrict__ Ylo)
{
    __shared__ alignas(16) float hs[2][NJ][BSL][HSL];   // 16 KB double-buffered h
    __shared__ alignas(16) float red[2][BSL][KC][HSL];  // 8 KB partial sums (2-deep)
    __shared__ alignas(16) float stage[2][BSL][HSL];    // 2 KB staging
    __shared__ alignas(8) unsigned long long mbar[2][NJ];

    const int j    = blockIdx.x;                 // hidden slice = cluster rank
    const int i    = blockIdx.y;                 // batch group
    const int tid  = threadIdx.x;
    const int kc   = tid >> 6;                   // warp-pair 0..3
    const int jloc = tid & 63;
    const int lane = tid & 31;
    const int w    = tid >> 5;                   // warp 0..7
    const int b0   = i * BSL;

    const uint32_t hs_base    = smem_u32(&hs[0][0][0][0]);
    const uint32_t mbar_base  = smem_u32(&mbar[0][0]);
    const uint32_t stage_base = smem_u32(&stage[0][0][0]);

    if (tid == 0) {
#pragma unroll
        for (int ph = 0; ph < 2; ph++)
#pragma unroll
            for (int s = 0; s < NJ; s++) {
                const uint32_t mb = mbar_base + (uint32_t)(ph * NJ + s) * 8;
                mbar_init(mb, 1);
                mbar_arrive_expect_tx(mb, SLICE_BYTES);
            }
    }
    asm volatile("barrier.cluster.arrive.aligned;" ::: "memory");
    asm volatile("barrier.cluster.wait.aligned;"  ::: "memory");

    // Per-lane peer addresses: lane r of EVERY warp maps cluster rank r.
    uint32_t peer_hs_l = 0, peer_mb_l = 0;
    if (lane < NJ) {
        peer_hs_l = mapa_u32(hs_base,   (uint32_t)lane);
        peer_mb_l = mapa_u32(mbar_base, (uint32_t)lane);
    }

    // Whh chunk in registers as packed (even,odd) pairs
    unsigned long long w2[64];
    {
        const float* wrow = Whh + (size_t)(j * HSL + jloc) * HH + kc * 128;
#pragma unroll
        for (int q = 0; q < 32; q++) {
            float4 v = *(const float4*)(wrow + q * 4);
            w2[q * 2 + 0] = pack_f2(v.x, v.y);
            w2[q * 2 + 1] = pack_f2(v.z, v.w);
        }
    }

    const int rb  = tid >> 6;
    const int rjj = tid & 63;
    const int brow = b0 + rb;
    const int jg   = j * HSL + rjj;
    const size_t zy_off = (size_t)brow * HH + jg;

    // Sub-offset of this warp's 128B stage chunk within a slice
    const uint32_t warp_sub = ((uint32_t)(w >> 1) * HSL + (uint32_t)(w & 1) * 32) * 4;

    const uint32_t mbA0 = mbar_base + (uint32_t)(0 * NJ + 2 * kc) * 8;
    const uint32_t mbA1 = mbar_base + (uint32_t)(1 * NJ + 2 * kc) * 8;

    int par[2] = {0, 0};

    for (int t = 0; t < TT; t++) {
        const int ph = t & 1;

        float zv = __ldcs(Z + (size_t)t * BB * HH + zy_off);

        float acc = 0.0f;
        if (t > 0) {
            const uint32_t mbA = (ph == 0) ? mbA0 : mbA1;   // slice 2kc
            const uint32_t mbB = mbA + 8;                    // slice 2kc+1
            const int p = par[ph];

            unsigned long long acc2[BSL];
#pragma unroll
            for (int b = 0; b < BSL; b++) acc2[b] = pack_f2(0.0f, 0.0f);

            // ---- slice 2kc ----
            mbar_wait_parity(mbA, p);
            {
                const int s = kc * 2;
#pragma unroll
                for (int b = 0; b < BSL; b++) {
                    const ulonglong2* hp = (const ulonglong2*)&hs[ph][s][b][0];
#pragma unroll
                    for (int q = 0; q < 16; q++) {
                        ulonglong2 hv = hp[q];
                        ffma2(acc2[b], hv.x, w2[q * 2 + 0]);
                        ffma2(acc2[b], hv.y, w2[q * 2 + 1]);
                    }
                }
            }
            // ---- slice 2kc+1 ----
            mbar_wait_parity(mbB, p);
            if (jloc == 0) {
                mbar_arrive_expect_tx(mbA, SLICE_BYTES);
                mbar_arrive_expect_tx(mbB, SLICE_BYTES);
            }
            {
                const int s = kc * 2 + 1;
#pragma unroll
                for (int b = 0; b < BSL; b++) {
                    const ulonglong2* hp = (const ulonglong2*)&hs[ph][s][b][0];
#pragma unroll
                    for (int q = 0; q < 16; q++) {
                        ulonglong2 hv = hp[q];
                        ffma2(acc2[b], hv.x, w2[32 + q * 2 + 0]);
                        ffma2(acc2[b], hv.y, w2[32 + q * 2 + 1]);
                    }
                }
            }
            par[ph] = p ^ 1;

#pragma unroll
            for (int b = 0; b < BSL; b++)
                red[ph][b][kc][jloc] = lo_f(acc2[b]) + hi_f(acc2[b]);
            __syncthreads();   // the ONLY per-step CTA barrier

#pragma unroll
            for (int c = 0; c < KC; c++) acc += red[ph][rb][c][rjj];
        }

        float val = tanhf(acc + zv);
        const size_t go = (size_t)t * BB * HH + zy_off;
        if (Yhi) {
            __nv_bfloat16 h = __float2bfloat16(val);
            Yhi[go] = h;
            Ylo[go] = __float2bfloat16(val - __bfloat162float(h));
        } else {
            Yf[go] = val;
        }

        // Per-warp early shipping: stage 128B chunk, then lanes 0..7 each
        // bulk-copy it to one peer CTA (tx-signal on the peer's mbarrier).
        if (t + 1 < TT) {
            stage[ph][rb][rjj] = val;
            __syncwarp();
            if (lane < NJ) {
                fence_proxy_async_cta();
                const uint32_t src = stage_base + (uint32_t)ph * SLICE_BYTES + warp_sub;
                const uint32_t dst = peer_hs_l
                    + (uint32_t)(ph ^ 1) * HS_BYTES + (uint32_t)j * SLICE_BYTES + warp_sub;
                const uint32_t mb  = peer_mb_l + (uint32_t)((ph ^ 1) * NJ + j) * 8;
                bulk_dsmem(dst, src, 128, mb);
            }
        }
    }

    asm volatile("barrier.cluster.arrive.aligned;" ::: "memory");
    asm volatile("barrier.cluster.wait.aligned;"  ::: "memory");
}

// ---------------------------------------------------------------------------
extern "C" void kernel_launch(void* const* d_in, const int* in_sizes, int n_in,
                              void* d_out, int out_size)
{
    const float* Xt   = (const float*)d_in[0];
    const float* ihW0 = (const float*)d_in[1];
    const float* ihB0 = (const float*)d_in[2];
    const float* hhW0 = (const float*)d_in[3];
    const float* hhB0 = (const float*)d_in[4];
    const float* ihW1 = (const float*)d_in[5];
    const float* ihB1 = (const float*)d_in[6];
    const float* hhW1 = (const float*)d_in[7];
    const float* hhB1 = (const float*)d_in[8];
    float* out = (float*)d_out;

    float *zp = nullptr;
    __nv_bfloat16 *ahi, *alo, *whi, *wlo;
    cudaGetSymbolAddress((void**)&zp,  g_Z);
    cudaGetSymbolAddress((void**)&ahi, g_Ahi);
    cudaGetSymbolAddress((void**)&alo, g_Alo);
    cudaGetSymbolAddress((void**)&whi, g_Whi);
    cudaGetSymbolAddress((void**)&wlo, g_Wlo);

    dim3 ggrid(TT * BB / 128, HH / 128);   // (512, 4)
    dim3 rgrid(NJ, NI);                    // (8, 16)

    const int NW = HH * DD;

    // ---- Layer 0 ----
    split_kernel<<<512, 256>>>(ihW0, whi, wlo, NW);
    mma_gemm_kernel<<<ggrid, 256>>>(Xt, nullptr, nullptr, whi, wlo, ihB0, hhB0, zp);
    recur_kernel<<<rgrid, 256>>>(zp, hhW0, nullptr, ahi, alo);

    // ---- Layer 1 ----
    split_kernel<<<512, 256>>>(ihW1, whi, wlo, NW);
    mma_gemm_kernel<<<ggrid, 256>>>(nullptr, ahi, alo, whi, wlo, ihB1, hhB1, zp);
    recur_kernel<<<rgrid, 256>>>(zp, hhW1, out, nullptr, nullptr);
}

// round 15
// speedup vs baseline: 1.3151x; 1.3151x over previous
#include <cuda_runtime.h>
#include <cuda_bf16.h>
#include <cstdint>
#include <cstddef>

#define TT 1024
#define BB 64
#define DD 512
#define HH 512

// Recurrence partition: NI batch-groups (clusters) x NJ hidden-slices
#define NI 16
#define NJ 8
#define BSL (BB / NI)        // 4 batch rows per group
#define HSL (HH / NJ)        // 64 hidden units per slice
#define RKC 8                // k-chunks of 64: warp w <-> slice w
#define SLICE_BYTES (BSL * HSL * 4)
#define HS_BYTES (NJ * SLICE_BYTES)

// Device scratch (no cudaMalloc allowed)
__device__ float g_Z [(size_t)TT * BB * HH];
__device__ __nv_bfloat16 g_Ahi[(size_t)TT * BB * DD];
__device__ __nv_bfloat16 g_Alo[(size_t)TT * BB * DD];
__device__ __nv_bfloat16 g_Whi[(size_t)HH * DD];
__device__ __nv_bfloat16 g_Wlo[(size_t)HH * DD];

// ---------------------------------------------------------------------------
// PTX helpers
// ---------------------------------------------------------------------------
__device__ __forceinline__ uint32_t smem_u32(const void* p) {
    uint32_t a;
    asm("{ .reg .u64 t; cvta.to.shared.u64 t, %1; cvt.u32.u64 %0, t; }"
        : "=r"(a) : "l"(p));
    return a;
}
__device__ __forceinline__ uint32_t mapa_u32(uint32_t addr, uint32_t rank) {
    uint32_t r;
    asm("mapa.shared::cluster.u32 %0, %1, %2;" : "=r"(r) : "r"(addr), "r"(rank));
    return r;
}
__device__ __forceinline__ void mbar_init(uint32_t mbar, uint32_t cnt) {
    asm volatile("mbarrier.init.shared.b64 [%0], %1;" :: "r"(mbar), "r"(cnt) : "memory");
}
__device__ __forceinline__ void mbar_arrive_expect_tx(uint32_t mbar, uint32_t tx) {
    asm volatile("mbarrier.arrive.expect_tx.shared.b64 _, [%0], %1;"
                 :: "r"(mbar), "r"(tx) : "memory");
}
__device__ __forceinline__ void mbar_wait_parity(uint32_t mbar, uint32_t parity) {
    asm volatile(
        "{\n\t"
        ".reg .pred P;\n\t"
        "WAIT_%=:\n\t"
        "mbarrier.try_wait.parity.acquire.cta.shared::cta.b64 P, [%0], %1, 0x989680;\n\t"
        "@P bra.uni DONE_%=;\n\t"
        "bra.uni WAIT_%=;\n\t"
        "DONE_%=:\n\t"
        "}"
        :: "r"(mbar), "r"(parity) : "memory");
}
__device__ __forceinline__ void bulk_dsmem(uint32_t dst_cluster, uint32_t src_cta,
                                           uint32_t bytes, uint32_t mbar_cluster) {
    asm volatile(
        "cp.async.bulk.shared::cluster.shared::cta.mbarrier::complete_tx::bytes "
        "[%0], [%1], %2, [%3];"
        :: "r"(dst_cluster), "r"(src_cta), "r"(bytes), "r"(mbar_cluster) : "memory");
}
__device__ __forceinline__ void fence_proxy_async_cta() {
    asm volatile("fence.proxy.async.shared::cta;" ::: "memory");
}
__device__ __forceinline__ void ffma2(unsigned long long& d,
                                      unsigned long long a, unsigned long long b) {
    asm("fma.rn.f32x2 %0, %1, %2, %0;" : "+l"(d) : "l"(a), "l"(b));
}
__device__ __forceinline__ unsigned long long pack_f2(float lo, float hi) {
    return (unsigned long long)__float_as_uint(lo) |
           ((unsigned long long)__float_as_uint(hi) << 32);
}
__device__ __forceinline__ float lo_f(unsigned long long v) {
    return __uint_as_float((unsigned int)v);
}
__device__ __forceinline__ float hi_f(unsigned long long v) {
    return __uint_as_float((unsigned int)(v >> 32));
}

// mma.sync m16n8k16 bf16 (sm_80+ baseline PTX: safe at compute_103)
__device__ __forceinline__ void mma16816(float* d, const uint32_t* a, const uint32_t* b) {
    asm volatile(
        "mma.sync.aligned.m16n8k16.row.col.f32.bf16.bf16.f32 "
        "{%0,%1,%2,%3}, {%4,%5,%6,%7}, {%8,%9}, {%0,%1,%2,%3};"
        : "+f"(d[0]), "+f"(d[1]), "+f"(d[2]), "+f"(d[3])
        : "r"(a[0]), "r"(a[1]), "r"(a[2]), "r"(a[3]), "r"(b[0]), "r"(b[1]));
}
__device__ __forceinline__ void ldsm_x4(uint32_t* r, uint32_t addr) {
    asm volatile("ldmatrix.sync.aligned.m8n8.x4.shared.b16 {%0,%1,%2,%3}, [%4];"
        : "=r"(r[0]), "=r"(r[1]), "=r"(r[2]), "=r"(r[3]) : "r"(addr));
}

// ---------------------------------------------------------------------------
// Split-bf16 conversion (weights only)
// ---------------------------------------------------------------------------
__global__ void split_kernel(const float* __restrict__ src,
                             __nv_bfloat16* __restrict__ hi,
                             __nv_bfloat16* __restrict__ lo, int n)
{
    int idx = blockIdx.x * blockDim.x + threadIdx.x;
    int stride = gridDim.x * blockDim.x;
    for (int i = idx; i < n; i += stride) {
        float x = src[i];
        __nv_bfloat16 h = __float2bfloat16(x);
        hi[i] = h;
        lo[i] = __float2bfloat16(x - __bfloat162float(h));
    }
}

// ---------------------------------------------------------------------------
// HMMA GEMM (EXACT R10 static-smem version — the 6440-us component)
// ---------------------------------------------------------------------------
#define KB 32
#define PAD 40

__global__ __launch_bounds__(256) void mma_gemm_kernel(
    const float* __restrict__ Af32,
    const __nv_bfloat16* __restrict__ Ahi, const __nv_bfloat16* __restrict__ Alo,
    const __nv_bfloat16* __restrict__ Whi, const __nv_bfloat16* __restrict__ Wlo,
    const float* __restrict__ b1, const float* __restrict__ b2,
    float* __restrict__ C)
{
    __shared__ __nv_bfloat16 sAh[128][PAD];
    __shared__ __nv_bfloat16 sAl[128][PAD];
    __shared__ __nv_bfloat16 sWh[128][PAD];
    __shared__ __nv_bfloat16 sWl[128][PAD];

    const int tid   = threadIdx.x;
    const int wid   = tid >> 5;
    const int lane  = tid & 31;
    const int m0    = blockIdx.x * 128;
    const int n0    = blockIdx.y * 128;
    const int wm    = (wid >> 2) * 64;
    const int wn    = (wid & 3) * 32;

    float acc[4][4][4];
#pragma unroll
    for (int i = 0; i < 4; i++)
#pragma unroll
        for (int j = 0; j < 4; j++)
#pragma unroll
            for (int r = 0; r < 4; r++) acc[i][j][r] = 0.0f;

    const int ar = lane & 15, ac = (lane >> 4) * 8;
    const int br = (lane & 7) + ((lane >> 4) << 3), bc = ((lane >> 3) & 1) * 8;

    for (int kb = 0; kb < DD / KB; kb++) {
        const int k0 = kb * KB;

        // ---- A tiles ----
        if (Af32) {
#pragma unroll
            for (int it = 0; it < 4; it++) {
                int idx = it * 256 + tid;
                int r   = idx >> 3;
                int c4  = (idx & 7) * 4;
                float4 v = *(const float4*)(Af32 + (size_t)(m0 + r) * DD + k0 + c4);
                __nv_bfloat16 hx = __float2bfloat16(v.x);
                __nv_bfloat16 hy = __float2bfloat16(v.y);
                __nv_bfloat16 hz = __float2bfloat16(v.z);
                __nv_bfloat16 hw = __float2bfloat16(v.w);
                *(__nv_bfloat162*)&sAh[r][c4]     = __nv_bfloat162(hx, hy);
                *(__nv_bfloat162*)&sAh[r][c4 + 2] = __nv_bfloat162(hz, hw);
                __nv_bfloat162 l0, l1;
                l0.x = __float2bfloat16(v.x - __bfloat162float(hx));
                l0.y = __float2bfloat16(v.y - __bfloat162float(hy));
                l1.x = __float2bfloat16(v.z - __bfloat162float(hz));
                l1.y = __float2bfloat16(v.w - __bfloat162float(hw));
                *(__nv_bfloat162*)&sAl[r][c4]     = l0;
                *(__nv_bfloat162*)&sAl[r][c4 + 2] = l1;
            }
        } else {
#pragma unroll
            for (int tile = 0; tile < 2; tile++) {
                const __nv_bfloat16* src = (tile == 0) ? Ahi : Alo;
                __nv_bfloat16 (*dst)[PAD] = (tile == 0) ? sAh : sAl;
#pragma unroll
                for (int it = 0; it < 2; it++) {
                    int idx = it * 256 + tid;
                    int r   = idx >> 2;
                    int c   = (idx & 3) * 8;
                    uint4 v = *(const uint4*)(src + (size_t)(m0 + r) * DD + k0 + c);
                    *(uint4*)&dst[r][c] = v;
                }
            }
        }

        // ---- W tiles ----
#pragma unroll
        for (int tile = 0; tile < 2; tile++) {
            const __nv_bfloat16* src = (tile == 0) ? Whi : Wlo;
            __nv_bfloat16 (*dst)[PAD] = (tile == 0) ? sWh : sWl;
#pragma unroll
            for (int it = 0; it < 2; it++) {
                int idx = it * 256 + tid;
                int r   = idx >> 2;
                int c   = (idx & 3) * 8;
                uint4 v = *(const uint4*)(src + (size_t)(n0 + r) * DD + k0 + c);
                *(uint4*)&dst[r][c] = v;
            }
        }
        __syncthreads();

#pragma unroll
        for (int ks = 0; ks < 2; ks++) {
            const int kk = ks * 16;
            uint32_t fAh[4][4], fAl[4][4], fWh[2][4], fWl[2][4];
#pragma unroll
            for (int mf = 0; mf < 4; mf++) {
                ldsm_x4(fAh[mf], smem_u32(&sAh[wm + mf * 16 + ar][kk + ac]));
                ldsm_x4(fAl[mf], smem_u32(&sAl[wm + mf * 16 + ar][kk + ac]));
            }
#pragma unroll
            for (int np = 0; np < 2; np++) {
                ldsm_x4(fWh[np], smem_u32(&sWh[wn + np * 16 + br][kk + bc]));
                ldsm_x4(fWl[np], smem_u32(&sWl[wn + np * 16 + br][kk + bc]));
            }
#pragma unroll
            for (int mf = 0; mf < 4; mf++) {
#pragma unroll
                for (int np = 0; np < 2; np++) {
#pragma unroll
                    for (int h = 0; h < 2; h++) {
                        const int nf = np * 2 + h;
                        mma16816(acc[mf][nf], fAh[mf], &fWh[np][h * 2]);
                        mma16816(acc[mf][nf], fAh[mf], &fWl[np][h * 2]);
                        mma16816(acc[mf][nf], fAl[mf], &fWh[np][h * 2]);
                    }
                }
            }
        }
        __syncthreads();
    }

    const int erow = lane >> 2;
    const int ecol = (lane & 3) * 2;
#pragma unroll
    for (int mf = 0; mf < 4; mf++) {
#pragma unroll
        for (int nf = 0; nf < 4; nf++) {
            const int n = n0 + wn + nf * 8 + ecol;
            const float bv0 = __ldg(b1 + n)     + __ldg(b2 + n);
            const float bv1 = __ldg(b1 + n + 1) + __ldg(b2 + n + 1);
            const int r0 = m0 + wm + mf * 16 + erow;
            float2 o0 = make_float2(acc[mf][nf][0] + bv0, acc[mf][nf][1] + bv1);
            float2 o1 = make_float2(acc[mf][nf][2] + bv0, acc[mf][nf][3] + bv1);
            *(float2*)(C + (size_t)r0 * HH + n)       = o0;
            *(float2*)(C + (size_t)(r0 + 8) * HH + n) = o1;
        }
    }
}

// ---------------------------------------------------------------------------
// Persistent recurrence kernel v7: 256 threads, warp w <-> slice/k-chunk w.
// Each lane computes TWO outputs (jloc = lane, lane+32) that share the same
// h operand: every 16B hs load now feeds 4 FFMA2 (was 2), halving smem-port
// traffic. One mbarrier wait per warp per step. Barriers/staging/shipping
// identical to the 6440-us structure (reduce-bar + stage-bar + one 1KB bulk).
// ---------------------------------------------------------------------------
__global__ __launch_bounds__(256, 1) __cluster_dims__(NJ, 1, 1)
void recur_kernel(
    const float* __restrict__ Z, const float* __restrict__ Whh,
    float* __restrict__ Yf,
    __nv_bfloat16* __restrict__ Yhi, __nv_bfloat16* __restrict__ Ylo)
{
    __shared__ alignas(16) float hs[2][NJ][BSL][HSL];   // 16 KB double-buffered h
    __shared__ alignas(16) float red[BSL][RKC][HSL];    // 8 KB partial sums
    __shared__ alignas(16) float stage[2][BSL][HSL];    // 2 KB staging
    __shared__ alignas(8) unsigned long long mbar[2][NJ];

    const int j    = blockIdx.x;                 // hidden slice = cluster rank
    const int i    = blockIdx.y;                 // batch group
    const int tid  = threadIdx.x;
    const int w    = tid >> 5;                   // warp 0..7 = k-chunk = slice
    const int lane = tid & 31;
    const int b0   = i * BSL;

    const uint32_t hs_base    = smem_u32(&hs[0][0][0][0]);
    const uint32_t mbar_base  = smem_u32(&mbar[0][0]);
    const uint32_t stage_base = smem_u32(&stage[0][0][0]);

    if (tid == 0) {
#pragma unroll
        for (int ph = 0; ph < 2; ph++)
#pragma unroll
            for (int s = 0; s < NJ; s++) {
                const uint32_t mb = mbar_base + (uint32_t)(ph * NJ + s) * 8;
                mbar_init(mb, 1);
                mbar_arrive_expect_tx(mb, SLICE_BYTES);
            }
    }
    asm volatile("barrier.cluster.arrive.aligned;" ::: "memory");
    asm volatile("barrier.cluster.wait.aligned;"  ::: "memory");

    uint32_t my_peer_hs = 0, my_peer_mb = 0;
    if (tid < NJ) {
        my_peer_hs = mapa_u32(hs_base,   (uint32_t)tid);
        my_peer_mb = mapa_u32(mbar_base, (uint32_t)tid);
    }

    // Weights for my TWO outputs (jloc = lane and lane+32), k in [w*64, w*64+64).
    unsigned long long w2a[32], w2b[32];
    {
        const float* wrowA = Whh + (size_t)(j * HSL + lane)      * HH + w * 64;
        const float* wrowB = Whh + (size_t)(j * HSL + lane + 32) * HH + w * 64;
#pragma unroll
        for (int q = 0; q < 16; q++) {
            float4 va = *(const float4*)(wrowA + q * 4);
            float4 vb = *(const float4*)(wrowB + q * 4);
            w2a[q * 2 + 0] = pack_f2(va.x, va.y);
            w2a[q * 2 + 1] = pack_f2(va.z, va.w);
            w2b[q * 2 + 0] = pack_f2(vb.x, vb.y);
            w2b[q * 2 + 1] = pack_f2(vb.z, vb.w);
        }
    }

    // Epilogue mapping: thread tid owns output (rb, rjj)
    const int rb  = tid >> 6;
    const int rjj = tid & 63;
    const int brow = b0 + rb;
    const int jg   = j * HSL + rjj;
    const size_t zy_off = (size_t)brow * HH + jg;

    // My slice barrier per phase
    const uint32_t mbP0 = mbar_base + (uint32_t)(0 * NJ + w) * 8;
    const uint32_t mbP1 = mbar_base + (uint32_t)(1 * NJ + w) * 8;

    int par[2] = {0, 0};

    for (int t = 0; t < TT; t++) {
        const int ph = t & 1;

        float zv = __ldcs(Z + (size_t)t * BB * HH + zy_off);

        float acc = 0.0f;
        if (t > 0) {
            const uint32_t mb = (ph == 0) ? mbP0 : mbP1;
            const int p = par[ph];

            // ONE wait: my slice's 1KB delivery
            mbar_wait_parity(mb, p);
            if (lane == 0) mbar_arrive_expect_tx(mb, SLICE_BYTES);
            par[ph] = p ^ 1;

            unsigned long long a2[BSL], b2[BSL];
#pragma unroll
            for (int b = 0; b < BSL; b++) { a2[b] = 0ull; b2[b] = 0ull; }
#pragma unroll
            for (int b = 0; b < BSL; b++) {
                const ulonglong2* hp = (const ulonglong2*)&hs[ph][w][b][0];
#pragma unroll
                for (int q = 0; q < 16; q++) {
                    ulonglong2 hv = hp[q];          // 16B feeds 4 FFMA2
                    ffma2(a2[b], hv.x, w2a[q * 2 + 0]);
                    ffma2(a2[b], hv.y, w2a[q * 2 + 1]);
                    ffma2(b2[b], hv.x, w2b[q * 2 + 0]);
                    ffma2(b2[b], hv.y, w2b[q * 2 + 1]);
                }
            }
#pragma unroll
            for (int b = 0; b < BSL; b++) {
                red[b][w][lane]      = lo_f(a2[b]) + hi_f(a2[b]);
                red[b][w][lane + 32] = lo_f(b2[b]) + hi_f(b2[b]);
            }
            __syncthreads();

#pragma unroll
            for (int c = 0; c < RKC; c++) acc += red[rb][c][rjj];
        }

        float val = tanhf(acc + zv);
        const size_t go = (size_t)t * BB * HH + zy_off;
        if (Yhi) {
            __nv_bfloat16 h = __float2bfloat16(val);
            Yhi[go] = h;
            Ylo[go] = __float2bfloat16(val - __bfloat162float(h));
        } else {
            Yf[go] = val;
        }

        if (t + 1 < TT) {
            const int sph = t & 1;
            stage[sph][rb][rjj] = val;
            __syncthreads();
            if (tid < NJ) {
                fence_proxy_async_cta();
                const uint32_t src = stage_base + (uint32_t)sph * SLICE_BYTES;
                const uint32_t dst = my_peer_hs
                    + (uint32_t)(ph ^ 1) * HS_BYTES + (uint32_t)j * SLICE_BYTES;
                const uint32_t mb  = my_peer_mb + (uint32_t)((ph ^ 1) * NJ + j) * 8;
                bulk_dsmem(dst, src, SLICE_BYTES, mb);
            }
        } else {
            __syncthreads();
        }
    }

    asm volatile("barrier.cluster.arrive.aligned;" ::: "memory");
    asm volatile("barrier.cluster.wait.aligned;"  ::: "memory");
}

// ---------------------------------------------------------------------------
extern "C" void kernel_launch(void* const* d_in, const int* in_sizes, int n_in,
                              void* d_out, int out_size)
{
    const float* Xt   = (const float*)d_in[0];
    const float* ihW0 = (const float*)d_in[1];
    const float* ihB0 = (const float*)d_in[2];
    const float* hhW0 = (const float*)d_in[3];
    const float* hhB0 = (const float*)d_in[4];
    const float* ihW1 = (const float*)d_in[5];
    const float* ihB1 = (const float*)d_in[6];
    const float* hhW1 = (const float*)d_in[7];
    const float* hhB1 = (const float*)d_in[8];
    float* out = (float*)d_out;

    float *zp = nullptr;
    __nv_bfloat16 *ahi, *alo, *whi, *wlo;
    cudaGetSymbolAddress((void**)&zp,  g_Z);
    cudaGetSymbolAddress((void**)&ahi, g_Ahi);
    cudaGetSymbolAddress((void**)&alo, g_Alo);
    cudaGetSymbolAddress((void**)&whi, g_Whi);
    cudaGetSymbolAddress((void**)&wlo, g_Wlo);

    dim3 ggrid(TT * BB / 128, HH / 128);   // (512, 4)
    dim3 rgrid(NJ, NI);                    // (8, 16)

    const int NW = HH * DD;

    // ---- Layer 0 ----
    split_kernel<<<512, 256>>>(ihW0, whi, wlo, NW);
    mma_gemm_kernel<<<ggrid, 256>>>(Xt, nullptr, nullptr, whi, wlo, ihB0, hhB0, zp);
    recur_kernel<<<rgrid, 256>>>(zp, hhW0, nullptr, ahi, alo);

    // ---- Layer 1 ----
    split_kernel<<<512, 256>>>(ihW1, whi, wlo, NW);
    mma_gemm_kernel<<<ggrid, 256>>>(nullptr, ahi, alo, whi, wlo, ihB1, hhB1, zp);
    recur_kernel<<<rgrid, 256>>>(zp, hhW1, out, nullptr, nullptr);
}

// round 16
// speedup vs baseline: 1.3485x; 1.0255x over previous
#include <cuda_runtime.h>
#include <cuda_bf16.h>
#include <cstdint>
#include <cstddef>

#define TT 1024
#define BB 64
#define DD 512
#define HH 512

// Recurrence partition: NI batch-groups (clusters) x NJ hidden-slices
#define NI 16
#define NJ 8
#define BSL (BB / NI)        // 4 batch rows per group
#define HSL (HH / NJ)        // 64 hidden units per slice
#define RKC 16               // reduce chunks: 8 warps x 2 half-warps
#define SLICE_BYTES (BSL * HSL * 4)
#define HS_BYTES (NJ * SLICE_BYTES)

// Device scratch (no cudaMalloc allowed)
__device__ float g_Z [(size_t)TT * BB * HH];
__device__ __nv_bfloat16 g_Ahi[(size_t)TT * BB * DD];
__device__ __nv_bfloat16 g_Alo[(size_t)TT * BB * DD];
__device__ __nv_bfloat16 g_Whi[(size_t)HH * DD];
__device__ __nv_bfloat16 g_Wlo[(size_t)HH * DD];

// ---------------------------------------------------------------------------
// PTX helpers
// ---------------------------------------------------------------------------
__device__ __forceinline__ uint32_t smem_u32(const void* p) {
    uint32_t a;
    asm("{ .reg .u64 t; cvta.to.shared.u64 t, %1; cvt.u32.u64 %0, t; }"
        : "=r"(a) : "l"(p));
    return a;
}
__device__ __forceinline__ uint32_t mapa_u32(uint32_t addr, uint32_t rank) {
    uint32_t r;
    asm("mapa.shared::cluster.u32 %0, %1, %2;" : "=r"(r) : "r"(addr), "r"(rank));
    return r;
}
__device__ __forceinline__ void mbar_init(uint32_t mbar, uint32_t cnt) {
    asm volatile("mbarrier.init.shared.b64 [%0], %1;" :: "r"(mbar), "r"(cnt) : "memory");
}
__device__ __forceinline__ void mbar_arrive_expect_tx(uint32_t mbar, uint32_t tx) {
    asm volatile("mbarrier.arrive.expect_tx.shared.b64 _, [%0], %1;"
                 :: "r"(mbar), "r"(tx) : "memory");
}
__device__ __forceinline__ void mbar_wait_parity(uint32_t mbar, uint32_t parity) {
    asm volatile(
        "{\n\t"
        ".reg .pred P;\n\t"
        "WAIT_%=:\n\t"
        "mbarrier.try_wait.parity.acquire.cta.shared::cta.b64 P, [%0], %1, 0x989680;\n\t"
        "@P bra.uni DONE_%=;\n\t"
        "bra.uni WAIT_%=;\n\t"
        "DONE_%=:\n\t"
        "}"
        :: "r"(mbar), "r"(parity) : "memory");
}
__device__ __forceinline__ void bulk_dsmem(uint32_t dst_cluster, uint32_t src_cta,
                                           uint32_t bytes, uint32_t mbar_cluster) {
    asm volatile(
        "cp.async.bulk.shared::cluster.shared::cta.mbarrier::complete_tx::bytes "
        "[%0], [%1], %2, [%3];"
        :: "r"(dst_cluster), "r"(src_cta), "r"(bytes), "r"(mbar_cluster) : "memory");
}
__device__ __forceinline__ void fence_proxy_async_cta() {
    asm volatile("fence.proxy.async.shared::cta;" ::: "memory");
}
__device__ __forceinline__ void ffma2(unsigned long long& d,
                                      unsigned long long a, unsigned long long b) {
    asm("fma.rn.f32x2 %0, %1, %2, %0;" : "+l"(d) : "l"(a), "l"(b));
}
__device__ __forceinline__ unsigned long long pack_f2(float lo, float hi) {
    return (unsigned long long)__float_as_uint(lo) |
           ((unsigned long long)__float_as_uint(hi) << 32);
}
__device__ __forceinline__ float lo_f(unsigned long long v) {
    return __uint_as_float((unsigned int)v);
}
__device__ __forceinline__ float hi_f(unsigned long long v) {
    return __uint_as_float((unsigned int)(v >> 32));
}

// mma.sync m16n8k16 bf16 (sm_80+ baseline PTX: safe at compute_103)
__device__ __forceinline__ void mma16816(float* d, const uint32_t* a, const uint32_t* b) {
    asm volatile(
        "mma.sync.aligned.m16n8k16.row.col.f32.bf16.bf16.f32 "
        "{%0,%1,%2,%3}, {%4,%5,%6,%7}, {%8,%9}, {%0,%1,%2,%3};"
        : "+f"(d[0]), "+f"(d[1]), "+f"(d[2]), "+f"(d[3])
        : "r"(a[0]), "r"(a[1]), "r"(a[2]), "r"(a[3]), "r"(b[0]), "r"(b[1]));
}
__device__ __forceinline__ void ldsm_x4(uint32_t* r, uint32_t addr) {
    asm volatile("ldmatrix.sync.aligned.m8n8.x4.shared.b16 {%0,%1,%2,%3}, [%4];"
        : "=r"(r[0]), "=r"(r[1]), "=r"(r[2]), "=r"(r[3]) : "r"(addr));
}

// ---------------------------------------------------------------------------
// Split-bf16 conversion (weights only)
// ---------------------------------------------------------------------------
__global__ void split_kernel(const float* __restrict__ src,
                             __nv_bfloat16* __restrict__ hi,
                             __nv_bfloat16* __restrict__ lo, int n)
{
    int idx = blockIdx.x * blockDim.x + threadIdx.x;
    int stride = gridDim.x * blockDim.x;
    for (int i = idx; i < n; i += stride) {
        float x = src[i];
        __nv_bfloat16 h = __float2bfloat16(x);
        hi[i] = h;
        lo[i] = __float2bfloat16(x - __bfloat162float(h));
    }
}

// ---------------------------------------------------------------------------
// HMMA GEMM (EXACT R10 static-smem version)
// ---------------------------------------------------------------------------
#define KB 32
#define PAD 40

__global__ __launch_bounds__(256) void mma_gemm_kernel(
    const float* __restrict__ Af32,
    const __nv_bfloat16* __restrict__ Ahi, const __nv_bfloat16* __restrict__ Alo,
    const __nv_bfloat16* __restrict__ Whi, const __nv_bfloat16* __restrict__ Wlo,
    const float* __restrict__ b1, const float* __restrict__ b2,
    float* __restrict__ C)
{
    __shared__ __nv_bfloat16 sAh[128][PAD];
    __shared__ __nv_bfloat16 sAl[128][PAD];
    __shared__ __nv_bfloat16 sWh[128][PAD];
    __shared__ __nv_bfloat16 sWl[128][PAD];

    const int tid   = threadIdx.x;
    const int wid   = tid >> 5;
    const int lane  = tid & 31;
    const int m0    = blockIdx.x * 128;
    const int n0    = blockIdx.y * 128;
    const int wm    = (wid >> 2) * 64;
    const int wn    = (wid & 3) * 32;

    float acc[4][4][4];
#pragma unroll
    for (int i = 0; i < 4; i++)
#pragma unroll
        for (int j = 0; j < 4; j++)
#pragma unroll
            for (int r = 0; r < 4; r++) acc[i][j][r] = 0.0f;

    const int ar = lane & 15, ac = (lane >> 4) * 8;
    const int br = (lane & 7) + ((lane >> 4) << 3), bc = ((lane >> 3) & 1) * 8;

    for (int kb = 0; kb < DD / KB; kb++) {
        const int k0 = kb * KB;

        // ---- A tiles ----
        if (Af32) {
#pragma unroll
            for (int it = 0; it < 4; it++) {
                int idx = it * 256 + tid;
                int r   = idx >> 3;
                int c4  = (idx & 7) * 4;
                float4 v = *(const float4*)(Af32 + (size_t)(m0 + r) * DD + k0 + c4);
                __nv_bfloat16 hx = __float2bfloat16(v.x);
                __nv_bfloat16 hy = __float2bfloat16(v.y);
                __nv_bfloat16 hz = __float2bfloat16(v.z);
                __nv_bfloat16 hw = __float2bfloat16(v.w);
                *(__nv_bfloat162*)&sAh[r][c4]     = __nv_bfloat162(hx, hy);
                *(__nv_bfloat162*)&sAh[r][c4 + 2] = __nv_bfloat162(hz, hw);
                __nv_bfloat162 l0, l1;
                l0.x = __float2bfloat16(v.x - __bfloat162float(hx));
                l0.y = __float2bfloat16(v.y - __bfloat162float(hy));
                l1.x = __float2bfloat16(v.z - __bfloat162float(hz));
                l1.y = __float2bfloat16(v.w - __bfloat162float(hw));
                *(__nv_bfloat162*)&sAl[r][c4]     = l0;
                *(__nv_bfloat162*)&sAl[r][c4 + 2] = l1;
            }
        } else {
#pragma unroll
            for (int tile = 0; tile < 2; tile++) {
                const __nv_bfloat16* src = (tile == 0) ? Ahi : Alo;
                __nv_bfloat16 (*dst)[PAD] = (tile == 0) ? sAh : sAl;
#pragma unroll
                for (int it = 0; it < 2; it++) {
                    int idx = it * 256 + tid;
                    int r   = idx >> 2;
                    int c   = (idx & 3) * 8;
                    uint4 v = *(const uint4*)(src + (size_t)(m0 + r) * DD + k0 + c);
                    *(uint4*)&dst[r][c] = v;
                }
            }
        }

        // ---- W tiles ----
#pragma unroll
        for (int tile = 0; tile < 2; tile++) {
            const __nv_bfloat16* src = (tile == 0) ? Whi : Wlo;
            __nv_bfloat16 (*dst)[PAD] = (tile == 0) ? sWh : sWl;
#pragma unroll
            for (int it = 0; it < 2; it++) {
                int idx = it * 256 + tid;
                int r   = idx >> 2;
                int c   = (idx & 3) * 8;
                uint4 v = *(const uint4*)(src + (size_t)(n0 + r) * DD + k0 + c);
                *(uint4*)&dst[r][c] = v;
            }
        }
        __syncthreads();

#pragma unroll
        for (int ks = 0; ks < 2; ks++) {
            const int kk = ks * 16;
            uint32_t fAh[4][4], fAl[4][4], fWh[2][4], fWl[2][4];
#pragma unroll
            for (int mf = 0; mf < 4; mf++) {
                ldsm_x4(fAh[mf], smem_u32(&sAh[wm + mf * 16 + ar][kk + ac]));
                ldsm_x4(fAl[mf], smem_u32(&sAl[wm + mf * 16 + ar][kk + ac]));
            }
#pragma unroll
            for (int np = 0; np < 2; np++) {
                ldsm_x4(fWh[np], smem_u32(&sWh[wn + np * 16 + br][kk + bc]));
                ldsm_x4(fWl[np], smem_u32(&sWl[wn + np * 16 + br][kk + bc]));
            }
#pragma unroll
            for (int mf = 0; mf < 4; mf++) {
#pragma unroll
                for (int np = 0; np < 2; np++) {
#pragma unroll
                    for (int h = 0; h < 2; h++) {
                        const int nf = np * 2 + h;
                        mma16816(acc[mf][nf], fAh[mf], &fWh[np][h * 2]);
                        mma16816(acc[mf][nf], fAh[mf], &fWl[np][h * 2]);
                        mma16816(acc[mf][nf], fAl[mf], &fWh[np][h * 2]);
                    }
                }
            }
        }
        __syncthreads();
    }

    const int erow = lane >> 2;
    const int ecol = (lane & 3) * 2;
#pragma unroll
    for (int mf = 0; mf < 4; mf++) {
#pragma unroll
        for (int nf = 0; nf < 4; nf++) {
            const int n = n0 + wn + nf * 8 + ecol;
            const float bv0 = __ldg(b1 + n)     + __ldg(b2 + n);
            const float bv1 = __ldg(b1 + n + 1) + __ldg(b2 + n + 1);
            const int r0 = m0 + wm + mf * 16 + erow;
            float2 o0 = make_float2(acc[mf][nf][0] + bv0, acc[mf][nf][1] + bv1);
            float2 o1 = make_float2(acc[mf][nf][2] + bv0, acc[mf][nf][3] + bv1);
            *(float2*)(C + (size_t)r0 * HH + n)       = o0;
            *(float2*)(C + (size_t)(r0 + 8) * HH + n) = o1;
        }
    }
}

// ---------------------------------------------------------------------------
// Persistent recurrence kernel v8: 256 threads, warp w <-> slice w, and each
// HALF-WARP covers a 32-k sub-chunk with each lane computing FOUR outputs
// (ll, ll+16, ll+32, ll+48). Every 16B hs load feeds 8 FFMA2 (was 4):
// LDS traffic halves again (64 -> 32 loads/lane/step).
// One mbarrier wait per warp per step; barriers/staging/1KB-bulk shipping
// identical to the 5381-us structure.
// ---------------------------------------------------------------------------
__global__ __launch_bounds__(256, 1) __cluster_dims__(NJ, 1, 1)
void recur_kernel(
    const float* __restrict__ Z, const float* __restrict__ Whh,
    float* __restrict__ Yf,
    __nv_bfloat16* __restrict__ Yhi, __nv_bfloat16* __restrict__ Ylo)
{
    __shared__ alignas(16) float hs[2][NJ][BSL][HSL];   // 16 KB double-buffered h
    __shared__ alignas(16) float red[BSL][RKC][HSL];    // 16 KB partial sums
    __shared__ alignas(16) float stage[2][BSL][HSL];    // 2 KB staging
    __shared__ alignas(8) unsigned long long mbar[2][NJ];

    const int j    = blockIdx.x;                 // hidden slice = cluster rank
    const int i    = blockIdx.y;                 // batch group
    const int tid  = threadIdx.x;
    const int w    = tid >> 5;                   // warp 0..7 = slice
    const int lane = tid & 31;
    const int hh   = lane >> 4;                  // half-warp 0/1 = 32-k sub-chunk
    const int ll   = lane & 15;                  // lane-in-half
    const int b0   = i * BSL;

    const uint32_t hs_base    = smem_u32(&hs[0][0][0][0]);
    const uint32_t mbar_base  = smem_u32(&mbar[0][0]);
    const uint32_t stage_base = smem_u32(&stage[0][0][0]);

    if (tid == 0) {
#pragma unroll
        for (int ph = 0; ph < 2; ph++)
#pragma unroll
            for (int s = 0; s < NJ; s++) {
                const uint32_t mb = mbar_base + (uint32_t)(ph * NJ + s) * 8;
                mbar_init(mb, 1);
                mbar_arrive_expect_tx(mb, SLICE_BYTES);
            }
    }
    asm volatile("barrier.cluster.arrive.aligned;" ::: "memory");
    asm volatile("barrier.cluster.wait.aligned;"  ::: "memory");

    uint32_t my_peer_hs = 0, my_peer_mb = 0;
    if (tid < NJ) {
        my_peer_hs = mapa_u32(hs_base,   (uint32_t)tid);
        my_peer_mb = mapa_u32(mbar_base, (uint32_t)tid);
    }

    // Weights for my FOUR outputs (j*64 + ll + o*16), k in [w*64+hh*32, +32).
    unsigned long long w4[4][16];
    {
        const int k0 = w * 64 + hh * 32;
#pragma unroll
        for (int o = 0; o < 4; o++) {
            const float* wrow = Whh + (size_t)(j * HSL + ll + o * 16) * HH + k0;
#pragma unroll
            for (int q = 0; q < 8; q++) {
                float4 v = *(const float4*)(wrow + q * 4);
                w4[o][q * 2 + 0] = pack_f2(v.x, v.y);
                w4[o][q * 2 + 1] = pack_f2(v.z, v.w);
            }
        }
    }

    // Epilogue mapping: thread tid owns output (rb, rjj)
    const int rb  = tid >> 6;
    const int rjj = tid & 63;
    const int brow = b0 + rb;
    const int jg   = j * HSL + rjj;
    const size_t zy_off = (size_t)brow * HH + jg;

    // My slice barrier per phase
    const uint32_t mbP0 = mbar_base + (uint32_t)(0 * NJ + w) * 8;
    const uint32_t mbP1 = mbar_base + (uint32_t)(1 * NJ + w) * 8;
    const int rc = w * 2 + hh;                   // my reduce-chunk row

    int par[2] = {0, 0};

    for (int t = 0; t < TT; t++) {
        const int ph = t & 1;

        float zv = __ldcs(Z + (size_t)t * BB * HH + zy_off);

        float acc = 0.0f;
        if (t > 0) {
            const uint32_t mb = (ph == 0) ? mbP0 : mbP1;
            const int p = par[ph];

            // ONE wait: my slice's 1KB delivery
            mbar_wait_parity(mb, p);
            if (lane == 0) mbar_arrive_expect_tx(mb, SLICE_BYTES);
            par[ph] = p ^ 1;

            unsigned long long a4[4][BSL];
#pragma unroll
            for (int o = 0; o < 4; o++)
#pragma unroll
                for (int b = 0; b < BSL; b++) a4[o][b] = 0ull;

#pragma unroll
            for (int b = 0; b < BSL; b++) {
                const ulonglong2* hp =
                    (const ulonglong2*)&hs[ph][w][b][hh * 32];   // 8 x 16B
#pragma unroll
                for (int q = 0; q < 8; q++) {
                    ulonglong2 hv = hp[q];          // 16B feeds 8 FFMA2
#pragma unroll
                    for (int o = 0; o < 4; o++) {
                        ffma2(a4[o][b], hv.x, w4[o][q * 2 + 0]);
                        ffma2(a4[o][b], hv.y, w4[o][q * 2 + 1]);
                    }
                }
            }
#pragma unroll
            for (int b = 0; b < BSL; b++)
#pragma unroll
                for (int o = 0; o < 4; o++)
                    red[b][rc][ll + o * 16] = lo_f(a4[o][b]) + hi_f(a4[o][b]);
            __syncthreads();

#pragma unroll
            for (int c = 0; c < RKC; c++) acc += red[rb][c][rjj];
        }

        float val = tanhf(acc + zv);
        const size_t go = (size_t)t * BB * HH + zy_off;
        if (Yhi) {
            __nv_bfloat16 h = __float2bfloat16(val);
            Yhi[go] = h;
            Ylo[go] = __float2bfloat16(val - __bfloat162float(h));
        } else {
            Yf[go] = val;
        }

        if (t + 1 < TT) {
            const int sph = t & 1;
            stage[sph][rb][rjj] = val;
            __syncthreads();
            if (tid < NJ) {
                fence_proxy_async_cta();
                const uint32_t src = stage_base + (uint32_t)sph * SLICE_BYTES;
                const uint32_t dst = my_peer_hs
                    + (uint32_t)(ph ^ 1) * HS_BYTES + (uint32_t)j * SLICE_BYTES;
                const uint32_t mb  = my_peer_mb + (uint32_t)((ph ^ 1) * NJ + j) * 8;
                bulk_dsmem(dst, src, SLICE_BYTES, mb);
            }
        } else {
            __syncthreads();
        }
    }

    asm volatile("barrier.cluster.arrive.aligned;" ::: "memory");
    asm volatile("barrier.cluster.wait.aligned;"  ::: "memory");
}

// ---------------------------------------------------------------------------
extern "C" void kernel_launch(void* const* d_in, const int* in_sizes, int n_in,
                              void* d_out, int out_size)
{
    const float* Xt   = (const float*)d_in[0];
    const float* ihW0 = (const float*)d_in[1];
    const float* ihB0 = (const float*)d_in[2];
    const float* hhW0 = (const float*)d_in[3];
    const float* hhB0 = (const float*)d_in[4];
    const float* ihW1 = (const float*)d_in[5];
    const float* ihB1 = (const float*)d_in[6];
    const float* hhW1 = (const float*)d_in[7];
    const float* hhB1 = (const float*)d_in[8];
    float* out = (float*)d_out;

    float *zp = nullptr;
    __nv_bfloat16 *ahi, *alo, *whi, *wlo;
    cudaGetSymbolAddress((void**)&zp,  g_Z);
    cudaGetSymbolAddress((void**)&ahi, g_Ahi);
    cudaGetSymbolAddress((void**)&alo, g_Alo);
    cudaGetSymbolAddress((void**)&whi, g_Whi);
    cudaGetSymbolAddress((void**)&wlo, g_Wlo);

    dim3 ggrid(TT * BB / 128, HH / 128);   // (512, 4)
    dim3 rgrid(NJ, NI);                    // (8, 16)

    const int NW = HH * DD;

    // ---- Layer 0 ----
    split_kernel<<<512, 256>>>(ihW0, whi, wlo, NW);
    mma_gemm_kernel<<<ggrid, 256>>>(Xt, nullptr, nullptr, whi, wlo, ihB0, hhB0, zp);
    recur_kernel<<<rgrid, 256>>>(zp, hhW0, nullptr, ahi, alo);

    // ---- Layer 1 ----
    split_kernel<<<512, 256>>>(ihW1, whi, wlo, NW);
    mma_gemm_kernel<<<ggrid, 256>>>(nullptr, ahi, alo, whi, wlo, ihB1, hhB1, zp);
    recur_kernel<<<rgrid, 256>>>(zp, hhW1, out, nullptr, nullptr);
}